// round 1
// baseline (speedup 1.0000x reference)
#include <cuda_runtime.h>
#include <cstdint>

#define EMA_OLD 0.01f
#define EMA_NEW 0.99f

#define MAXB 4096
#define MAXN 1024

// Scratch (allocation-free rule: __device__ globals)
__device__ unsigned long long g_best[MAXB];   // packed (sortable_score << 32) | j
__device__ int                g_winner[MAXN]; // max b with z[b]==j, or -1
__device__ float              g_mnorm[MAXN];  // ||m_j||^2

// ---------------------------------------------------------------------------
__global__ void init_kernel(int B, int n) {
    int i = blockIdx.x * blockDim.x + threadIdx.x;
    if (i < B) g_best[i] = 0xFFFFFFFFFFFFFFFFull;
    if (i < n) g_winner[i] = -1;
}

// ---------------------------------------------------------------------------
__global__ void mnorm_kernel(const float* __restrict__ M, int D) {
    int j = blockIdx.x;
    const float* row = M + (size_t)j * D;
    float s = 0.f;
    for (int d = threadIdx.x; d < D; d += blockDim.x) {
        float v = row[d];
        s = fmaf(v, v, s);
    }
    __shared__ float sh[256];
    sh[threadIdx.x] = s;
    __syncthreads();
    for (int off = 128; off > 0; off >>= 1) {
        if (threadIdx.x < off) sh[threadIdx.x] += sh[threadIdx.x + off];
        __syncthreads();
    }
    if (threadIdx.x == 0) g_mnorm[j] = sh[0];
}

// ---------------------------------------------------------------------------
// Fused SGEMM (y @ m^T) + row argmin of (||m_j||^2 - 2 * y_b . m_j).
// Tile 128x128, BK=16, 256 threads, 8x8 per-thread microtile.
#define BM 128
#define BN 128
#define BK 16
#define TM 8
#define TN 8

__device__ __forceinline__ unsigned fkey(float f) {
    unsigned u = __float_as_uint(f);
    return (u & 0x80000000u) ? ~u : (u | 0x80000000u);  // order-preserving
}

__global__ __launch_bounds__(256, 2)
void gemm_argmin_kernel(const float* __restrict__ Y,
                        const float* __restrict__ M,
                        int D) {
    __shared__ float As[BK][BM + 4];
    __shared__ float Bs[BK][BN + 4];

    const int tid = threadIdx.x;
    const int tx = tid & 15;   // col group (j)
    const int ty = tid >> 4;   // row group (b)
    const int brow = blockIdx.y * BM;  // y rows
    const int bcol = blockIdx.x * BN;  // m rows (cluster j)

    float acc[TM][TN];
#pragma unroll
    for (int i = 0; i < TM; i++)
#pragma unroll
        for (int j = 0; j < TN; j++) acc[i][j] = 0.f;

    const float* Yb = Y + (size_t)brow * D;
    const float* Mb = M + (size_t)bcol * D;

    for (int k0 = 0; k0 < D; k0 += BK) {
        // Load 128x16 tiles of Y and M (512 float4 each, 2 per thread), transposed.
#pragma unroll
        for (int it = 0; it < 2; it++) {
            int v = tid + it * 256;
            int row = v >> 2;      // 0..127
            int c4 = v & 3;        // 0..3  (float4 column within BK)
            float4 a = *(const float4*)(Yb + (size_t)row * D + k0 + c4 * 4);
            As[c4 * 4 + 0][row] = a.x;
            As[c4 * 4 + 1][row] = a.y;
            As[c4 * 4 + 2][row] = a.z;
            As[c4 * 4 + 3][row] = a.w;
            float4 b = *(const float4*)(Mb + (size_t)row * D + k0 + c4 * 4);
            Bs[c4 * 4 + 0][row] = b.x;
            Bs[c4 * 4 + 1][row] = b.y;
            Bs[c4 * 4 + 2][row] = b.z;
            Bs[c4 * 4 + 3][row] = b.w;
        }
        __syncthreads();

#pragma unroll
        for (int k = 0; k < BK; k++) {
            float af[TM], bf[TN];
#pragma unroll
            for (int i = 0; i < TM; i += 4) {
                float4 t = *(const float4*)&As[k][ty * TM + i];
                af[i] = t.x; af[i + 1] = t.y; af[i + 2] = t.z; af[i + 3] = t.w;
            }
#pragma unroll
            for (int j = 0; j < TN; j += 4) {
                float4 t = *(const float4*)&Bs[k][tx * TN + j];
                bf[j] = t.x; bf[j + 1] = t.y; bf[j + 2] = t.z; bf[j + 3] = t.w;
            }
#pragma unroll
            for (int i = 0; i < TM; i++)
#pragma unroll
                for (int j = 0; j < TN; j++)
                    acc[i][j] = fmaf(af[i], bf[j], acc[i][j]);
        }
        __syncthreads();
    }

    // Scores and fused argmin.
    float mn[TN];
#pragma unroll
    for (int j = 0; j < TN; j++) mn[j] = g_mnorm[bcol + tx * TN + j];

#pragma unroll
    for (int i = 0; i < TM; i++) {
        unsigned long long pk = 0xFFFFFFFFFFFFFFFFull;
#pragma unroll
        for (int j = 0; j < TN; j++) {
            float sc = mn[j] - 2.0f * acc[i][j];
            unsigned long long cand =
                ((unsigned long long)fkey(sc) << 32) |
                (unsigned)(bcol + tx * TN + j);
            pk = (cand < pk) ? cand : pk;
        }
        // Reduce across the 16 tx-lanes sharing this row (xor stays in-warp).
#pragma unroll
        for (int off = 1; off < 16; off <<= 1) {
            unsigned long long o = __shfl_xor_sync(0xFFFFFFFFu, pk, off);
            pk = (o < pk) ? o : pk;
        }
        if (tx == 0)
            atomicMin(&g_best[brow + ty * TM + i], pk);
    }
}

// ---------------------------------------------------------------------------
__global__ void winner_kernel(int B) {
    int b = blockIdx.x * blockDim.x + threadIdx.x;
    if (b < B) {
        int z = (int)(g_best[b] & 0xFFFFFFFFull);
        atomicMax(&g_winner[z], b);   // last-write-wins => max b
    }
}

// ---------------------------------------------------------------------------
// out[j]     = winner ? m[j]*0.01 + y[w]*0.99            : m[j]
// out[n+j]   = winner ? (new_m - y[w])^2*0.01 + sd*0.99  : sd[j]
__global__ void output_kernel(const float* __restrict__ Y,
                              const float* __restrict__ M,
                              const float* __restrict__ SD,
                              float* __restrict__ out,
                              int D, int n) {
    int j = blockIdx.x;
    int w = g_winner[j];
    int D4 = D >> 2;
    const float4* mrow  = (const float4*)(M  + (size_t)j * D);
    const float4* sdrow = (const float4*)(SD + (size_t)j * D);
    float4* om = (float4*)(out + (size_t)j * D);
    float4* os = (float4*)(out + (size_t)(n + j) * D);

    if (w < 0) {
        for (int d = threadIdx.x; d < D4; d += blockDim.x) {
            om[d] = mrow[d];
            os[d] = sdrow[d];
        }
    } else {
        const float4* yrow = (const float4*)(Y + (size_t)w * D);
        for (int d = threadIdx.x; d < D4; d += blockDim.x) {
            float4 mv = mrow[d], yv = yrow[d], sv = sdrow[d];
            float4 nm, ns;
            nm.x = mv.x * EMA_OLD + yv.x * EMA_NEW;
            nm.y = mv.y * EMA_OLD + yv.y * EMA_NEW;
            nm.z = mv.z * EMA_OLD + yv.z * EMA_NEW;
            nm.w = mv.w * EMA_OLD + yv.w * EMA_NEW;
            float dx = nm.x - yv.x, dy = nm.y - yv.y,
                  dz = nm.z - yv.z, dw = nm.w - yv.w;
            ns.x = dx * dx * EMA_OLD + sv.x * EMA_NEW;
            ns.y = dy * dy * EMA_OLD + sv.y * EMA_NEW;
            ns.z = dz * dz * EMA_OLD + sv.z * EMA_NEW;
            ns.w = dw * dw * EMA_OLD + sv.w * EMA_NEW;
            om[d] = nm;
            os[d] = ns;
        }
    }
}

// ---------------------------------------------------------------------------
extern "C" void kernel_launch(void* const* d_in, const int* in_sizes, int n_in,
                              void* d_out, int out_size) {
    const float* y  = (const float*)d_in[0];
    const float* m  = (const float*)d_in[1];
    const float* sd = (const float*)d_in[2];
    // d_in[3] = p — unused by the reference output.
    (void)n_in; (void)out_size;

    const int n = in_sizes[3];            // 1024
    const int D = in_sizes[1] / n;        // 4096
    const int B = in_sizes[0] / D;        // 4096
    float* out = (float*)d_out;

    int initN = (B > n ? B : n);
    init_kernel<<<(initN + 255) / 256, 256>>>(B, n);
    mnorm_kernel<<<n, 256>>>(m, D);

    dim3 grid(n / BN, B / BM);
    gemm_argmin_kernel<<<grid, 256>>>(y, m, D);

    winner_kernel<<<(B + 255) / 256, 256>>>(B);
    output_kernel<<<n, 256>>>(y, m, sd, out, D, n);
}